// round 14
// baseline (speedup 1.0000x reference)
#include <cuda_runtime.h>
#include <cuda_fp16.h>
#include <cstdint>
#include <math.h>

#define SEQ 2048
#define DIM 1024
#define NHEADS 8
#define HD 128
#define LOG2E 1.4426950408889634f
#define INV_TAU 0.088388347648318447f

// ---------------- scratch (device globals; no allocation) ----------------
__device__ float g_itilde[NHEADS * SEQ];
__device__ float g_logsig[NHEADS * SEQ];
__device__ float g_a2[NHEADS * SEQ];      // a_j * log2(e)
__device__ float g_M2[NHEADS * SEQ];      // M_i * log2(e)
__device__ float g_nfloor[NHEADS * SEQ];  // exp(-(csum_i + M_i))
__device__ __half g_o16[2][SEQ * DIM];    // fp16 partial O per column-parity
__device__ float g_bpart[2][NHEADS * SEQ];
__device__ __half g_q16[SEQ * DIM];       // fp16 copies (written by gates_kernel)
__device__ __half g_k16[SEQ * DIM];
__device__ __half g_v16[SEQ * DIM];
__device__ int g_cnt[NHEADS * 16];        // arrival counters per (head, row-tile)

// ---------------- smem layout (bytes). Row pitch = 136 fp16 = 272 B ----------------
#define PITCH 272
#define OFF_Q 0            /* 128 x 272 = 34816 */
#define OFF_KV 34816       /* 3 buffers x (K 17408 + V 17408) */
#define KVB_STRIDE 34816
#define V_IN_BUF 17408
#define OFF_EA (OFF_KV + 3 * KVB_STRIDE)  /* 3 x 68 floats */
#define EAF (OFF_EA / 4)
#define OFF_FLAG (OFF_EA + 3 * 272)
#define FLAGF (OFF_FLAG / 4)
#define SMEM_TOTAL (OFF_FLAG + 16)

// ---------------- helpers ----------------
__device__ __forceinline__ uint32_t smem_u32(const void* p) {
    uint32_t a;
    asm("{ .reg .u64 t; cvta.to.shared.u64 t, %1; cvt.u32.u64 %0, t; }" : "=r"(a) : "l"(p));
    return a;
}
__device__ __forceinline__ void cp16(uint32_t dst, const void* src) {
    asm volatile("cp.async.cg.shared.global [%0], [%1], 16;" :: "r"(dst), "l"(src));
}
#define CP_COMMIT() asm volatile("cp.async.commit_group;" ::: "memory")
#define CP_WAIT(n) asm volatile("cp.async.wait_group %0;" :: "n"(n) : "memory")
__device__ __forceinline__ void ldsm4(uint32_t* r, uint32_t addr) {
    asm volatile("ldmatrix.sync.aligned.m8n8.x4.shared.b16 {%0,%1,%2,%3}, [%4];"
                 : "=r"(r[0]), "=r"(r[1]), "=r"(r[2]), "=r"(r[3]) : "r"(addr));
}
__device__ __forceinline__ void ldsm4t(uint32_t* r, uint32_t addr) {
    asm volatile("ldmatrix.sync.aligned.m8n8.x4.trans.shared.b16 {%0,%1,%2,%3}, [%4];"
                 : "=r"(r[0]), "=r"(r[1]), "=r"(r[2]), "=r"(r[3]) : "r"(addr));
}
__device__ __forceinline__ void mma16816(float* d, const uint32_t* a, const uint32_t* b) {
    asm volatile(
        "mma.sync.aligned.m16n8k16.row.col.f32.f16.f16.f32 "
        "{%0,%1,%2,%3}, {%4,%5,%6,%7}, {%8,%9}, {%0,%1,%2,%3};"
        : "+f"(d[0]), "+f"(d[1]), "+f"(d[2]), "+f"(d[3])
        : "r"(a[0]), "r"(a[1]), "r"(a[2]), "r"(a[3]), "r"(b[0]), "r"(b[1]));
}
__device__ __forceinline__ uint32_t pack_hf2(float a, float b) {
    __half2 t = __floats2half2_rn(a, b);
    return *reinterpret_cast<uint32_t*>(&t);
}

// ---------------- kernel A: gate projections + fp16 conversion (8 tokens/block) ----------------
__global__ void gates_kernel(const float* __restrict__ q, const float* __restrict__ k,
                             const float* __restrict__ v,
                             const float* __restrict__ Wi_w, const float* __restrict__ Wi_b,
                             const float* __restrict__ Wf_w, const float* __restrict__ Wf_b) {
    const int s0 = blockIdx.x * 8;
    const int h = threadIdx.x >> 5;
    const int lane = threadIdx.x & 31;
    const float* wi = Wi_w + h * 3 * DIM;
    const float* wf = Wf_w + h * 3 * DIM;

    float si[8], sf[8];
#pragma unroll
    for (int t = 0; t < 8; t++) { si[t] = 0.f; sf[t] = 0.f; }

#pragma unroll
    for (int m = 0; m < 8; m++) {
        const int d = m * 128 + lane * 4;
        const float4 wi0 = *reinterpret_cast<const float4*>(wi + d);
        const float4 wi1 = *reinterpret_cast<const float4*>(wi + DIM + d);
        const float4 wi2 = *reinterpret_cast<const float4*>(wi + 2 * DIM + d);
        const float4 wf0 = *reinterpret_cast<const float4*>(wf + d);
        const float4 wf1 = *reinterpret_cast<const float4*>(wf + DIM + d);
        const float4 wf2 = *reinterpret_cast<const float4*>(wf + 2 * DIM + d);

#pragma unroll
        for (int t = 0; t < 8; t++) {
            const size_t base = (size_t)(s0 + t) * DIM + d;
            const float4 xq = *reinterpret_cast<const float4*>(q + base);
            const float4 xk = *reinterpret_cast<const float4*>(k + base);
            const float4 xv = *reinterpret_cast<const float4*>(v + base);

            if (h == 0) {
                *reinterpret_cast<uint2*>(g_q16 + base) =
                    make_uint2(pack_hf2(xq.x, xq.y), pack_hf2(xq.z, xq.w));
            } else if (h == 1) {
                *reinterpret_cast<uint2*>(g_k16 + base) =
                    make_uint2(pack_hf2(xk.x, xk.y), pack_hf2(xk.z, xk.w));
            } else if (h == 2) {
                *reinterpret_cast<uint2*>(g_v16 + base) =
                    make_uint2(pack_hf2(xv.x, xv.y), pack_hf2(xv.z, xv.w));
            }

            si[t] += xq.x * wi0.x + xq.y * wi0.y + xq.z * wi0.z + xq.w * wi0.w;
            si[t] += xk.x * wi1.x + xk.y * wi1.y + xk.z * wi1.z + xk.w * wi1.w;
            si[t] += xv.x * wi2.x + xv.y * wi2.y + xv.z * wi2.z + xv.w * wi2.w;
            sf[t] += xq.x * wf0.x + xq.y * wf0.y + xq.z * wf0.z + xq.w * wf0.w;
            sf[t] += xk.x * wf1.x + xk.y * wf1.y + xk.z * wf1.z + xk.w * wf1.w;
            sf[t] += xv.x * wf2.x + xv.y * wf2.y + xv.z * wf2.z + xv.w * wf2.w;
        }
    }
#pragma unroll
    for (int t = 0; t < 8; t++) {
#pragma unroll
        for (int o = 16; o; o >>= 1) {
            si[t] += __shfl_xor_sync(0xffffffffu, si[t], o);
            sf[t] += __shfl_xor_sync(0xffffffffu, sf[t], o);
        }
    }
    if (lane == 0) {
#pragma unroll
        for (int t = 0; t < 8; t++) {
            const int s = s0 + t;
            g_itilde[h * SEQ + s] = si[t] + Wi_b[h];
            const float ft = sf[t] + Wf_b[h];
            g_logsig[h * SEQ + s] = fminf(ft, 0.f) - log1pf(__expf(-fabsf(ft)));
        }
    }
}

// ---------------- kernel B: per-head scans + counter reset ----------------
__global__ void scan_kernel() {
    const int h = blockIdx.x;
    const int t = threadIdx.x;
    __shared__ float sc[256];

    if (t < 16) g_cnt[h * 16 + t] = 0;  // reset merge counters every replay

    float cs[8];
    float run = 0.f;
#pragma unroll
    for (int m = 0; m < 8; m++) {
        run += g_logsig[h * SEQ + t * 8 + m];
        cs[m] = run;
    }
    sc[t] = run;
    __syncthreads();
#pragma unroll
    for (int off = 1; off < 256; off <<= 1) {
        const float vv = sc[t];
        const float uu = (t >= off) ? sc[t - off] : 0.f;
        __syncthreads();
        sc[t] = vv + uu;
        __syncthreads();
    }
    const float base = (t == 0) ? 0.f : sc[t - 1];

    float a[8], amax[8], csum[8];
    float runm = -3.402823466e38f;
#pragma unroll
    for (int m = 0; m < 8; m++) {
        csum[m] = base + cs[m];
        a[m] = g_itilde[h * SEQ + t * 8 + m] - csum[m];
        runm = fmaxf(runm, a[m]);
        amax[m] = runm;
    }
    __syncthreads();
    sc[t] = runm;
    __syncthreads();
#pragma unroll
    for (int off = 1; off < 256; off <<= 1) {
        const float vv = sc[t];
        const float uu = (t >= off) ? sc[t - off] : -3.402823466e38f;
        __syncthreads();
        sc[t] = fmaxf(vv, uu);
        __syncthreads();
    }
    const float mbase = (t == 0) ? -3.402823466e38f : sc[t - 1];

#pragma unroll
    for (int m = 0; m < 8; m++) {
        const int j = h * SEQ + t * 8 + m;
        const float Mv = fmaxf(mbase, amax[m]);
        g_a2[j] = a[m] * LOG2E;
        g_M2[j] = Mv * LOG2E;
        g_nfloor[j] = exp2f(-(csum[m] + Mv) * LOG2E);
    }
}

// issue one K/V column tile (64 rows) into stage buffer via cp.async
__device__ __forceinline__ void issue_kv(uint32_t sb, float* smf, int j0, int h, int hb,
                                         uint32_t kvb, int eaF, int tid) {
#pragma unroll
    for (int m = 0; m < 8; m++) {
        const int idx = tid + m * 256;          // 0..2047
        const int row = (idx >> 4) & 63;        // 64 rows per half
        const int chunk = idx & 15;             // 16 x 16B per row
        if (idx < 1024) {
            cp16(sb + kvb + row * PITCH + chunk * 16,
                 g_k16 + (size_t)(j0 + row) * DIM + h * HD + chunk * 8);
        } else {
            cp16(sb + kvb + V_IN_BUF + row * PITCH + chunk * 16,
                 g_v16 + (size_t)(j0 + row) * DIM + h * HD + chunk * 8);
        }
    }
    if (tid < 64) smf[eaF + tid] = exp2f(g_a2[hb + j0 + tid] - g_M2[hb + j0 + 63]);
    if (tid == 64) smf[eaF + 64] = g_M2[hb + j0 + 63];
}

// ---------------- main kernel: fp16 HMMA flash mLSTM + fused merge/GroupNorm ----------------
// grid (16, 8): blockIdx.x = pair p (>>1) + column parity (&1); blockIdx.y = head.
__global__ void __launch_bounds__(256, 1)
mlstm_mma(float* __restrict__ out, const float* __restrict__ gn_w,
          const float* __restrict__ gn_b) {
    extern __shared__ char smraw[];
    const uint32_t sb = smem_u32(smraw);
    float* smf = reinterpret_cast<float*>(smraw);
    int* smi = reinterpret_cast<int*>(smraw);

    const int tid = threadIdx.x;
    const int lane = tid & 31;
    const int warp = tid >> 5;
    const int qc = lane & 3;
    const int h = blockIdx.y, hb = h * SEQ;
    const int p = blockIdx.x >> 1, par = blockIdx.x & 1;
    const int m0 = warp * 16;

    const uint32_t offA = (uint32_t)(m0 + (lane & 15)) * PITCH + ((lane >> 4) * 8) * 2;
    const uint32_t offB = (uint32_t)(((lane >> 4) & 1) * 8 + (lane & 7)) * PITCH +
                          (((lane >> 3) & 1) * 8) * 2;
    const uint32_t offV = (uint32_t)(lane & 15) * PITCH + ((lane >> 4) * 8) * 2;

    for (int hs = 0; hs < 2; hs++) {
        const int rtc = hs ? (15 - p) : p;
        const int i0 = rtc * 128;
        const int n_ct = 2 * rtc + 2;

        if (hs) __syncthreads();  // protect Q/KV/ea buffers from previous half

        // --- prologue: group0 = Q + tile0, group1 = tile1 (possibly empty) ---
#pragma unroll
        for (int m = 0; m < 8; m++) {
            const int idx = tid + m * 256;      // 0..2047
            const int row = idx >> 4;           // 128 rows
            const int chunk = idx & 15;
            cp16(sb + OFF_Q + row * PITCH + chunk * 16,
                 g_q16 + (size_t)(i0 + row) * DIM + h * HD + chunk * 8);
        }
        issue_kv(sb, smf, par * 64, h, hb, OFF_KV, EAF, tid);
        CP_COMMIT();
        if (par + 2 < n_ct)
            issue_kv(sb, smf, (par + 2) * 64, h, hb, OFF_KV + KVB_STRIDE, EAF + 68, tid);
        CP_COMMIT();

        const int r_lo = i0 + m0 + (lane >> 2);
        const int r_hi = r_lo + 8;
        const float m2_lo = g_M2[hb + r_lo];
        const float m2_hi = g_M2[hb + r_hi];

        float accO[16][4];
#pragma unroll
        for (int a = 0; a < 16; a++)
#pragma unroll
            for (int b = 0; b < 4; b++) accO[a][b] = 0.f;
        float bsl = 0.f, bsh = 0.f;

        uint32_t qfrag[8][4];   // Q fragments, loaded once per half
        bool qloaded = false;

        for (int ct = par, it = 0; ct < n_ct; ct += 2, it++) {
            const int j0 = ct * 64;
            int buf = it % 3;
            const uint32_t kvb = OFF_KV + (uint32_t)buf * KVB_STRIDE;
            const int eaF = EAF + buf * 68;

            CP_WAIT(1);        // tile it complete (1 newer group may stay pending)
            __syncthreads();   // publish tile it; all warps done with buffer (it+2)%3

            if (ct + 4 < n_ct) {
                const int nbuf = (it + 2) % 3;
                issue_kv(sb, smf, (ct + 4) * 64, h, hb,
                         OFF_KV + (uint32_t)nbuf * KVB_STRIDE, EAF + nbuf * 68, tid);
            }
            CP_COMMIT();       // always: uniform group accounting

            if (!qloaded) {
                qloaded = true;
#pragma unroll
                for (int kt = 0; kt < 8; kt++) ldsm4(qfrag[kt], sb + OFF_Q + offA + kt * 32);
            }

            const bool fskip = (ct == 2 * rtc + 1) && (warp < 4);
            if (!fskip) {
                // --- GEMM1: S = Q K^T (fp16, Q from registers) ---
                float accS[8][4];
#pragma unroll
                for (int a = 0; a < 8; a++)
#pragma unroll
                    for (int b = 0; b < 4; b++) accS[a][b] = 0.f;

#pragma unroll
                for (int kt = 0; kt < 8; kt++) {
#pragma unroll
                    for (int np2 = 0; np2 < 2; np2++) {
                        const uint32_t b0a = sb + kvb + offB + (2 * np2) * (16 * PITCH) + kt * 32;
                        const uint32_t b1a = b0a + 16 * PITCH;
                        uint32_t bh0[4], bh1[4];
                        ldsm4(bh0, b0a);
                        ldsm4(bh1, b1a);
                        float* a0 = accS[4 * np2];
                        float* a1 = accS[4 * np2 + 1];
                        float* a2 = accS[4 * np2 + 2];
                        float* a3 = accS[4 * np2 + 3];
                        mma16816(a0, qfrag[kt], bh0); mma16816(a2, qfrag[kt], bh1);
                        mma16816(a1, qfrag[kt], bh0 + 2); mma16816(a3, qfrag[kt], bh1 + 2);
                    }
                }

                // --- decay weights (incl. 1/tau) + causal mask + rowsum ---
                const float ref2 = smf[eaF + 64];
                const float em_lo = exp2f(ref2 - m2_lo) * INV_TAU;
                const float em_hi = exp2f(ref2 - m2_hi) * INV_TAU;
                const bool diag = (ct >= 2 * rtc);
#pragma unroll
                for (int nt = 0; nt < 8; nt++) {
                    const int col0 = nt * 8 + 2 * qc;
                    const float w0 = smf[eaF + col0], w1 = smf[eaF + col0 + 1];
                    float* c = accS[nt];
                    float p00 = c[0] * w0 * em_lo, p01 = c[1] * w1 * em_lo;
                    float p10 = c[2] * w0 * em_hi, p11 = c[3] * w1 * em_hi;
                    if (diag) {
                        const int jc = j0 + col0;
                        if (jc > r_lo) p00 = 0.f;
                        if (jc + 1 > r_lo) p01 = 0.f;
                        if (jc > r_hi) p10 = 0.f;
                        if (jc + 1 > r_hi) p11 = 0.f;
                    }
                    bsl += p00 + p01;
                    bsh += p10 + p11;
                    c[0] = p00; c[1] = p01; c[2] = p10; c[3] = p11;
                }

                // --- GEMM2: O += P V (fp16, interleaved accumulators) ---
#pragma unroll
                for (int kt2 = 0; kt2 < 4; kt2++) {
                    const float* s0 = accS[2 * kt2];
                    const float* s1 = accS[2 * kt2 + 1];
                    uint32_t ph[4];
                    ph[0] = pack_hf2(s0[0], s0[1]);
                    ph[1] = pack_hf2(s0[2], s0[3]);
                    ph[2] = pack_hf2(s1[0], s1[1]);
                    ph[3] = pack_hf2(s1[2], s1[3]);
#pragma unroll
                    for (int dpp = 0; dpp < 4; dpp++) {
                        const uint32_t v0a = sb + kvb + V_IN_BUF + offV + kt2 * (16 * PITCH) + (2 * dpp) * 32;
                        const uint32_t v1a = v0a + 32;
                        uint32_t vh0[4], vh1[4];
                        ldsm4t(vh0, v0a);
                        ldsm4t(vh1, v1a);
                        float* o0 = accO[4 * dpp];
                        float* o1 = accO[4 * dpp + 1];
                        float* o2 = accO[4 * dpp + 2];
                        float* o3 = accO[4 * dpp + 3];
                        mma16816(o0, ph, vh0); mma16816(o2, ph, vh1);
                        mma16816(o1, ph, vh0 + 2); mma16816(o3, ph, vh1 + 2);
                    }
                }
            }
        }

        // --- reduce rowsums across quad, store partials (fp16 O) ---
        bsl += __shfl_xor_sync(0xffffffffu, bsl, 1);
        bsl += __shfl_xor_sync(0xffffffffu, bsl, 2);
        bsh += __shfl_xor_sync(0xffffffffu, bsh, 1);
        bsh += __shfl_xor_sync(0xffffffffu, bsh, 2);
        if (qc == 0) {
            g_bpart[par][hb + r_lo] = bsl;
            g_bpart[par][hb + r_hi] = bsh;
        }
        __half* od = g_o16[par];
#pragma unroll
        for (int dt = 0; dt < 16; dt++) {
            const int col = h * HD + dt * 8 + 2 * qc;
            *reinterpret_cast<uint32_t*>(od + (size_t)r_lo * DIM + col) =
                pack_hf2(accO[dt][0], accO[dt][1]);
            *reinterpret_cast<uint32_t*>(od + (size_t)r_hi * DIM + col) =
                pack_hf2(accO[dt][2], accO[dt][3]);
        }

        // --- last-arriver merges + GroupNorm for this (h, rtc) block ---
        __threadfence();   // make this thread's partial stores globally visible
        __syncthreads();   // all threads' stores fenced before the arrival
        if (tid == 0) smi[FLAGF] = atomicAdd(&g_cnt[h * 16 + rtc], 1);
        __syncthreads();
        if (smi[FLAGF] == 1) {
            __threadfence();  // acquire: other CTA's stores now visible
            const float4 w = *reinterpret_cast<const float4*>(gn_w + h * HD + lane * 4);
            const float4 bb = *reinterpret_cast<const float4*>(gn_b + h * HD + lane * 4);
#pragma unroll 4
            for (int rr = 0; rr < 16; rr++) {
                const int s = i0 + warp * 16 + rr;
                const size_t off = (size_t)s * DIM + h * HD + lane * 4;

                const uint2 ar = *reinterpret_cast<const uint2*>(g_o16[0] + off);
                const uint2 br = *reinterpret_cast<const uint2*>(g_o16[1] + off);
                const float2 a0 = __half22float2(*reinterpret_cast<const __half2*>(&ar.x));
                const float2 a1 = __half22float2(*reinterpret_cast<const __half2*>(&ar.y));
                const float2 b0 = __half22float2(*reinterpret_cast<const __half2*>(&br.x));
                const float2 b1 = __half22float2(*reinterpret_cast<const __half2*>(&br.y));

                const float bs = g_bpart[0][hb + s] + g_bpart[1][hb + s];
                const float inv = 1.0f / (fmaxf(fabsf(bs), g_nfloor[hb + s]) + 1e-6f);

                float4 x;
                x.x = (a0.x + b0.x) * inv;
                x.y = (a0.y + b0.y) * inv;
                x.z = (a1.x + b1.x) * inv;
                x.w = (a1.y + b1.y) * inv;

                float sum = x.x + x.y + x.z + x.w;
#pragma unroll
                for (int o = 16; o; o >>= 1) sum += __shfl_xor_sync(0xffffffffu, sum, o);
                const float mean = sum * (1.0f / 128.0f);
                const float d0 = x.x - mean, d1 = x.y - mean, d2 = x.z - mean, d3 = x.w - mean;
                float sq = d0 * d0 + d1 * d1 + d2 * d2 + d3 * d3;
#pragma unroll
                for (int o = 16; o; o >>= 1) sq += __shfl_xor_sync(0xffffffffu, sq, o);
                const float istd = rsqrtf(sq * (1.0f / 128.0f) + 1e-5f);

                float4 y;
                y.x = d0 * istd * w.x + bb.x;
                y.y = d1 * istd * w.y + bb.y;
                y.z = d2 * istd * w.z + bb.z;
                y.w = d3 * istd * w.w + bb.w;
                *reinterpret_cast<float4*>(out + off) = y;
            }
        }
    }
}

// ---------------- launch ----------------
extern "C" void kernel_launch(void* const* d_in, const int* in_sizes, int n_in,
                              void* d_out, int out_size) {
    const float* q = (const float*)d_in[0];
    const float* k = (const float*)d_in[1];
    const float* v = (const float*)d_in[2];
    const float* Wi_w = (const float*)d_in[3];
    const float* Wi_b = (const float*)d_in[4];
    const float* Wf_w = (const float*)d_in[5];
    const float* Wf_b = (const float*)d_in[6];
    const float* gn_w = (const float*)d_in[7];
    const float* gn_b = (const float*)d_in[8];
    float* out = (float*)d_out;

    gates_kernel<<<SEQ / 8, 256>>>(q, k, v, Wi_w, Wi_b, Wf_w, Wf_b);
    scan_kernel<<<NHEADS, 256>>>();

    cudaFuncSetAttribute(mlstm_mma, cudaFuncAttributeMaxDynamicSharedMemorySize, SMEM_TOTAL);
    dim3 grid(16, NHEADS);
    mlstm_mma<<<grid, 256, SMEM_TOTAL>>>(out, gn_w, gn_b);
}

// round 15
// speedup vs baseline: 1.2233x; 1.2233x over previous
#include <cuda_runtime.h>
#include <cuda_fp16.h>
#include <cstdint>
#include <math.h>

#define SEQ 2048
#define DIM 1024
#define NHEADS 8
#define HD 128
#define LOG2E 1.4426950408889634f
#define INV_TAU 0.088388347648318447f

// ---------------- scratch (device globals; no allocation) ----------------
__device__ float g_itilde[NHEADS * SEQ];
__device__ float g_logsig[NHEADS * SEQ];
__device__ float g_a2[NHEADS * SEQ];      // a_j * log2(e)
__device__ float g_M2[NHEADS * SEQ];      // M_i * log2(e)
__device__ float g_nfloor[NHEADS * SEQ];  // exp(-(csum_i + M_i))
__device__ float g_tinfo[NHEADS][32][68]; // per (head, col-tile): ea[0..63], ref2, pad
__device__ __half g_o16[2][SEQ * DIM];    // fp16 partial O per column-parity
__device__ float g_bpart[2][NHEADS * SEQ];
__device__ __half g_q16[SEQ * DIM];       // fp16 copies (written by gates_kernel)
__device__ __half g_k16[SEQ * DIM];
__device__ __half g_v16[SEQ * DIM];

// ---------------- smem layout (bytes). Row pitch = 136 fp16 = 272 B ----------------
#define PITCH 272
#define OFF_Q 0            /* 128 x 272 = 34816 */
#define OFF_KV 34816       /* 3 buffers x (K 17408 + V 17408) */
#define KVB_STRIDE 34816
#define V_IN_BUF 17408
#define OFF_EA (OFF_KV + 3 * KVB_STRIDE)  /* 3 x 68 floats (tinfo per buffer) */
#define EAF (OFF_EA / 4)
#define SMEM_TOTAL (OFF_EA + 3 * 272)

// ---------------- helpers ----------------
__device__ __forceinline__ uint32_t smem_u32(const void* p) {
    uint32_t a;
    asm("{ .reg .u64 t; cvta.to.shared.u64 t, %1; cvt.u32.u64 %0, t; }" : "=r"(a) : "l"(p));
    return a;
}
__device__ __forceinline__ void cp16(uint32_t dst, const void* src) {
    asm volatile("cp.async.cg.shared.global [%0], [%1], 16;" :: "r"(dst), "l"(src));
}
#define CP_COMMIT() asm volatile("cp.async.commit_group;" ::: "memory")
#define CP_WAIT(n) asm volatile("cp.async.wait_group %0;" :: "n"(n) : "memory")
__device__ __forceinline__ void ldsm4(uint32_t* r, uint32_t addr) {
    asm volatile("ldmatrix.sync.aligned.m8n8.x4.shared.b16 {%0,%1,%2,%3}, [%4];"
                 : "=r"(r[0]), "=r"(r[1]), "=r"(r[2]), "=r"(r[3]) : "r"(addr));
}
__device__ __forceinline__ void ldsm4t(uint32_t* r, uint32_t addr) {
    asm volatile("ldmatrix.sync.aligned.m8n8.x4.trans.shared.b16 {%0,%1,%2,%3}, [%4];"
                 : "=r"(r[0]), "=r"(r[1]), "=r"(r[2]), "=r"(r[3]) : "r"(addr));
}
__device__ __forceinline__ void mma16816(float* d, const uint32_t* a, const uint32_t* b) {
    asm volatile(
        "mma.sync.aligned.m16n8k16.row.col.f32.f16.f16.f32 "
        "{%0,%1,%2,%3}, {%4,%5,%6,%7}, {%8,%9}, {%0,%1,%2,%3};"
        : "+f"(d[0]), "+f"(d[1]), "+f"(d[2]), "+f"(d[3])
        : "r"(a[0]), "r"(a[1]), "r"(a[2]), "r"(a[3]), "r"(b[0]), "r"(b[1]));
}
__device__ __forceinline__ uint32_t pack_hf2(float a, float b) {
    __half2 t = __floats2half2_rn(a, b);
    return *reinterpret_cast<uint32_t*>(&t);
}

// ---------------- kernel A: gate projections + fp16 conversion (1 token/block) ----------------
__global__ void gates_kernel(const float* __restrict__ q, const float* __restrict__ k,
                             const float* __restrict__ v,
                             const float* __restrict__ Wi_w, const float* __restrict__ Wi_b,
                             const float* __restrict__ Wf_w, const float* __restrict__ Wf_b) {
    const int s = blockIdx.x;
    const int h = threadIdx.x >> 5;
    const int lane = threadIdx.x & 31;
    const float* wi = Wi_w + h * 3 * DIM;
    const float* wf = Wf_w + h * 3 * DIM;
    const float* qr = q + (size_t)s * DIM;
    const float* kr = k + (size_t)s * DIM;
    const float* vr = v + (size_t)s * DIM;

    float si = 0.f, sf = 0.f;
#pragma unroll
    for (int m = 0; m < 8; m++) {
        const int d = m * 128 + lane * 4;
        const float4 xq = *reinterpret_cast<const float4*>(qr + d);
        const float4 xk = *reinterpret_cast<const float4*>(kr + d);
        const float4 xv = *reinterpret_cast<const float4*>(vr + d);

        if (h == 0) {
            *reinterpret_cast<uint2*>(g_q16 + (size_t)s * DIM + d) =
                make_uint2(pack_hf2(xq.x, xq.y), pack_hf2(xq.z, xq.w));
        } else if (h == 1) {
            *reinterpret_cast<uint2*>(g_k16 + (size_t)s * DIM + d) =
                make_uint2(pack_hf2(xk.x, xk.y), pack_hf2(xk.z, xk.w));
        } else if (h == 2) {
            *reinterpret_cast<uint2*>(g_v16 + (size_t)s * DIM + d) =
                make_uint2(pack_hf2(xv.x, xv.y), pack_hf2(xv.z, xv.w));
        }

        float4 w0 = *reinterpret_cast<const float4*>(wi + d);
        float4 w1 = *reinterpret_cast<const float4*>(wi + DIM + d);
        float4 w2 = *reinterpret_cast<const float4*>(wi + 2 * DIM + d);
        si += xq.x * w0.x + xq.y * w0.y + xq.z * w0.z + xq.w * w0.w;
        si += xk.x * w1.x + xk.y * w1.y + xk.z * w1.z + xk.w * w1.w;
        si += xv.x * w2.x + xv.y * w2.y + xv.z * w2.z + xv.w * w2.w;
        w0 = *reinterpret_cast<const float4*>(wf + d);
        w1 = *reinterpret_cast<const float4*>(wf + DIM + d);
        w2 = *reinterpret_cast<const float4*>(wf + 2 * DIM + d);
        sf += xq.x * w0.x + xq.y * w0.y + xq.z * w0.z + xq.w * w0.w;
        sf += xk.x * w1.x + xk.y * w1.y + xk.z * w1.z + xk.w * w1.w;
        sf += xv.x * w2.x + xv.y * w2.y + xv.z * w2.z + xv.w * w2.w;
    }
#pragma unroll
    for (int o = 16; o; o >>= 1) {
        si += __shfl_xor_sync(0xffffffffu, si, o);
        sf += __shfl_xor_sync(0xffffffffu, sf, o);
    }
    if (lane == 0) {
        g_itilde[h * SEQ + s] = si + Wi_b[h];
        const float ft = sf + Wf_b[h];
        g_logsig[h * SEQ + s] = fminf(ft, 0.f) - log1pf(__expf(-fabsf(ft)));
    }
}

// ---------------- kernel B: per-head scans + tile-info precompute ----------------
__global__ void scan_kernel() {
    const int h = blockIdx.x;
    const int t = threadIdx.x;
    __shared__ float sc[256];

    float cs[8];
    float run = 0.f;
#pragma unroll
    for (int m = 0; m < 8; m++) {
        run += g_logsig[h * SEQ + t * 8 + m];
        cs[m] = run;
    }
    sc[t] = run;
    __syncthreads();
#pragma unroll
    for (int off = 1; off < 256; off <<= 1) {
        const float vv = sc[t];
        const float uu = (t >= off) ? sc[t - off] : 0.f;
        __syncthreads();
        sc[t] = vv + uu;
        __syncthreads();
    }
    const float base = (t == 0) ? 0.f : sc[t - 1];

    float a[8], amax[8], csum[8];
    float runm = -3.402823466e38f;
#pragma unroll
    for (int m = 0; m < 8; m++) {
        csum[m] = base + cs[m];
        a[m] = g_itilde[h * SEQ + t * 8 + m] - csum[m];
        runm = fmaxf(runm, a[m]);
        amax[m] = runm;
    }
    __syncthreads();
    sc[t] = runm;
    __syncthreads();
#pragma unroll
    for (int off = 1; off < 256; off <<= 1) {
        const float vv = sc[t];
        const float uu = (t >= off) ? sc[t - off] : -3.402823466e38f;
        __syncthreads();
        sc[t] = fmaxf(vv, uu);
        __syncthreads();
    }
    const float mbase = (t == 0) ? -3.402823466e38f : sc[t - 1];

    float a2v[8];
#pragma unroll
    for (int m = 0; m < 8; m++) {
        const int j = h * SEQ + t * 8 + m;
        const float Mv = fmaxf(mbase, amax[m]);
        a2v[m] = a[m] * LOG2E;
        g_a2[j] = a2v[m];
        g_M2[j] = Mv * LOG2E;
        g_nfloor[j] = exp2f(-(csum[m] + Mv) * LOG2E);
    }
    __syncthreads();  // g_M2 writes visible block-wide

    // tile info: thread t owns tokens t*8..t*8+7, all within tile (t>>3)
    {
        const int tile = t >> 3;
        const float ref2 = g_M2[h * SEQ + tile * 64 + 63];
#pragma unroll
        for (int m = 0; m < 8; m++)
            g_tinfo[h][tile][(t & 7) * 8 + m] = exp2f(a2v[m] - ref2);
        if ((t & 7) == 7) g_tinfo[h][tile][64] = ref2;
    }
}

// issue one K/V column tile (64 rows) + its tinfo into stage buffer via cp.async
__device__ __forceinline__ void issue_kv(uint32_t sb, int j0, int h, int hb,
                                         uint32_t kvb, uint32_t eaB, int tid) {
#pragma unroll
    for (int m = 0; m < 8; m++) {
        const int idx = tid + m * 256;          // 0..2047
        const int row = (idx >> 4) & 63;        // 64 rows per half
        const int chunk = idx & 15;             // 16 x 16B per row
        if (idx < 1024) {
            cp16(sb + kvb + row * PITCH + chunk * 16,
                 g_k16 + (size_t)(j0 + row) * DIM + h * HD + chunk * 8);
        } else {
            cp16(sb + kvb + V_IN_BUF + row * PITCH + chunk * 16,
                 g_v16 + (size_t)(j0 + row) * DIM + h * HD + chunk * 8);
        }
    }
    if (tid < 17)
        cp16(sb + eaB + tid * 16, &g_tinfo[h][j0 >> 6][tid * 4]);
}

// ---------------- main kernel: fp16 HMMA flash mLSTM, 3-stage pipeline ----------------
// grid (16, 8): blockIdx.x = pair p (>>1) + column parity (&1); blockIdx.y = head.
__global__ void __launch_bounds__(256, 1)
mlstm_mma() {
    extern __shared__ char smraw[];
    const uint32_t sb = smem_u32(smraw);
    float* smf = reinterpret_cast<float*>(smraw);

    const int tid = threadIdx.x;
    const int lane = tid & 31;
    const int warp = tid >> 5;
    const int qc = lane & 3;
    const int h = blockIdx.y, hb = h * SEQ;
    const int p = blockIdx.x >> 1, par = blockIdx.x & 1;
    const int m0 = warp * 16;

    const uint32_t offA = (uint32_t)(m0 + (lane & 15)) * PITCH + ((lane >> 4) * 8) * 2;
    const uint32_t offB = (uint32_t)(((lane >> 4) & 1) * 8 + (lane & 7)) * PITCH +
                          (((lane >> 3) & 1) * 8) * 2;
    const uint32_t offV = (uint32_t)(lane & 15) * PITCH + ((lane >> 4) * 8) * 2;

    for (int hs = 0; hs < 2; hs++) {
        const int rtc = hs ? (15 - p) : p;
        const int i0 = rtc * 128;
        const int n_ct = 2 * rtc + 2;

        if (hs) __syncthreads();  // protect Q/KV/ea buffers from previous half

        // --- prologue: group0 = Q + tile0, group1 = tile1 (possibly empty) ---
#pragma unroll
        for (int m = 0; m < 8; m++) {
            const int idx = tid + m * 256;      // 0..2047
            const int row = idx >> 4;           // 128 rows
            const int chunk = idx & 15;
            cp16(sb + OFF_Q + row * PITCH + chunk * 16,
                 g_q16 + (size_t)(i0 + row) * DIM + h * HD + chunk * 8);
        }
        issue_kv(sb, par * 64, h, hb, OFF_KV, OFF_EA, tid);
        CP_COMMIT();
        if (par + 2 < n_ct)
            issue_kv(sb, (par + 2) * 64, h, hb, OFF_KV + KVB_STRIDE, OFF_EA + 272, tid);
        CP_COMMIT();

        const int r_lo = i0 + m0 + (lane >> 2);
        const int r_hi = r_lo + 8;
        const float m2_lo = g_M2[hb + r_lo];
        const float m2_hi = g_M2[hb + r_hi];

        float accO[16][4];
#pragma unroll
        for (int a = 0; a < 16; a++)
#pragma unroll
            for (int b = 0; b < 4; b++) accO[a][b] = 0.f;
        float bsl = 0.f, bsh = 0.f;

        uint32_t qfrag[8][4];   // Q fragments, loaded once per half
        bool qloaded = false;

        for (int ct = par, it = 0; ct < n_ct; ct += 2, it++) {
            const int j0 = ct * 64;
            const int buf = it % 3;
            const uint32_t kvb = OFF_KV + (uint32_t)buf * KVB_STRIDE;
            const int eaF = EAF + buf * 68;

            CP_WAIT(1);        // tile it complete (1 newer group may stay pending)
            __syncthreads();   // publish tile it; all warps done with buffer (it+2)%3

            if (ct + 4 < n_ct) {
                const int nbuf = (it + 2) % 3;
                issue_kv(sb, (ct + 4) * 64, h, hb,
                         OFF_KV + (uint32_t)nbuf * KVB_STRIDE, OFF_EA + nbuf * 272, tid);
            }
            CP_COMMIT();       // always: uniform group accounting

            if (!qloaded) {
                qloaded = true;
#pragma unroll
                for (int kt = 0; kt < 8; kt++) ldsm4(qfrag[kt], sb + OFF_Q + offA + kt * 32);
            }

            const bool fskip = (ct == 2 * rtc + 1) && (warp < 4);
            if (!fskip) {
                // --- GEMM1: S = Q K^T (fp16, Q from registers) ---
                float accS[8][4];
#pragma unroll
                for (int a = 0; a < 8; a++)
#pragma unroll
                    for (int b = 0; b < 4; b++) accS[a][b] = 0.f;

#pragma unroll
                for (int kt = 0; kt < 8; kt++) {
#pragma unroll
                    for (int np2 = 0; np2 < 2; np2++) {
                        const uint32_t b0a = sb + kvb + offB + (2 * np2) * (16 * PITCH) + kt * 32;
                        const uint32_t b1a = b0a + 16 * PITCH;
                        uint32_t bh0[4], bh1[4];
                        ldsm4(bh0, b0a);
                        ldsm4(bh1, b1a);
                        float* a0 = accS[4 * np2];
                        float* a1 = accS[4 * np2 + 1];
                        float* a2 = accS[4 * np2 + 2];
                        float* a3 = accS[4 * np2 + 3];
                        mma16816(a0, qfrag[kt], bh0); mma16816(a2, qfrag[kt], bh1);
                        mma16816(a1, qfrag[kt], bh0 + 2); mma16816(a3, qfrag[kt], bh1 + 2);
                    }
                }

                // --- decay weights (incl. 1/tau) + causal mask + rowsum ---
                const float ref2 = smf[eaF + 64];
                const float em_lo = exp2f(ref2 - m2_lo) * INV_TAU;
                const float em_hi = exp2f(ref2 - m2_hi) * INV_TAU;
                const bool diag = (ct >= 2 * rtc);
#pragma unroll
                for (int nt = 0; nt < 8; nt++) {
                    const int col0 = nt * 8 + 2 * qc;
                    const float w0 = smf[eaF + col0], w1 = smf[eaF + col0 + 1];
                    float* c = accS[nt];
                    float p00 = c[0] * w0 * em_lo, p01 = c[1] * w1 * em_lo;
                    float p10 = c[2] * w0 * em_hi, p11 = c[3] * w1 * em_hi;
                    if (diag) {
                        const int jc = j0 + col0;
                        if (jc > r_lo) p00 = 0.f;
                        if (jc + 1 > r_lo) p01 = 0.f;
                        if (jc > r_hi) p10 = 0.f;
                        if (jc + 1 > r_hi) p11 = 0.f;
                    }
                    bsl += p00 + p01;
                    bsh += p10 + p11;
                    c[0] = p00; c[1] = p01; c[2] = p10; c[3] = p11;
                }

                // --- GEMM2: O += P V (fp16, interleaved accumulators) ---
#pragma unroll
                for (int kt2 = 0; kt2 < 4; kt2++) {
                    const float* s0 = accS[2 * kt2];
                    const float* s1 = accS[2 * kt2 + 1];
                    uint32_t ph[4];
                    ph[0] = pack_hf2(s0[0], s0[1]);
                    ph[1] = pack_hf2(s0[2], s0[3]);
                    ph[2] = pack_hf2(s1[0], s1[1]);
                    ph[3] = pack_hf2(s1[2], s1[3]);
#pragma unroll
                    for (int dpp = 0; dpp < 4; dpp++) {
                        const uint32_t v0a = sb + kvb + V_IN_BUF + offV + kt2 * (16 * PITCH) + (2 * dpp) * 32;
                        const uint32_t v1a = v0a + 32;
                        uint32_t vh0[4], vh1[4];
                        ldsm4t(vh0, v0a);
                        ldsm4t(vh1, v1a);
                        float* o0 = accO[4 * dpp];
                        float* o1 = accO[4 * dpp + 1];
                        float* o2 = accO[4 * dpp + 2];
                        float* o3 = accO[4 * dpp + 3];
                        mma16816(o0, ph, vh0); mma16816(o2, ph, vh1);
                        mma16816(o1, ph, vh0 + 2); mma16816(o3, ph, vh1 + 2);
                    }
                }
            }
        }

        // --- reduce rowsums across quad, store partials (fp16 O) ---
        bsl += __shfl_xor_sync(0xffffffffu, bsl, 1);
        bsl += __shfl_xor_sync(0xffffffffu, bsl, 2);
        bsh += __shfl_xor_sync(0xffffffffu, bsh, 1);
        bsh += __shfl_xor_sync(0xffffffffu, bsh, 2);
        if (qc == 0) {
            g_bpart[par][hb + r_lo] = bsl;
            g_bpart[par][hb + r_hi] = bsh;
        }
        __half* od = g_o16[par];
#pragma unroll
        for (int dt = 0; dt < 16; dt++) {
            const int col = h * HD + dt * 8 + 2 * qc;
            *reinterpret_cast<uint32_t*>(od + (size_t)r_lo * DIM + col) =
                pack_hf2(accO[dt][0], accO[dt][1]);
            *reinterpret_cast<uint32_t*>(od + (size_t)r_hi * DIM + col) =
                pack_hf2(accO[dt][2], accO[dt][3]);
        }
    }
}

// ---------------- merge + denominator + GroupNorm (1 token/block) ----------------
__global__ void merge_gn(float* __restrict__ out, const float* __restrict__ gn_w,
                         const float* __restrict__ gn_b) {
    const int s = blockIdx.x;
    const int h = threadIdx.x >> 5;
    const int lane = threadIdx.x & 31;
    const size_t off = (size_t)s * DIM + h * HD + lane * 4;

    const uint2 ar = *reinterpret_cast<const uint2*>(g_o16[0] + off);
    const uint2 br = *reinterpret_cast<const uint2*>(g_o16[1] + off);
    const float2 a0 = __half22float2(*reinterpret_cast<const __half2*>(&ar.x));
    const float2 a1 = __half22float2(*reinterpret_cast<const __half2*>(&ar.y));
    const float2 b0 = __half22float2(*reinterpret_cast<const __half2*>(&br.x));
    const float2 b1 = __half22float2(*reinterpret_cast<const __half2*>(&br.y));

    const float bs = g_bpart[0][h * SEQ + s] + g_bpart[1][h * SEQ + s];
    const float inv = 1.0f / (fmaxf(fabsf(bs), g_nfloor[h * SEQ + s]) + 1e-6f);

    float4 x;
    x.x = (a0.x + b0.x) * inv;
    x.y = (a0.y + b0.y) * inv;
    x.z = (a1.x + b1.x) * inv;
    x.w = (a1.y + b1.y) * inv;

    float sum = x.x + x.y + x.z + x.w;
#pragma unroll
    for (int o = 16; o; o >>= 1) sum += __shfl_xor_sync(0xffffffffu, sum, o);
    const float mean = sum * (1.0f / 128.0f);
    const float d0 = x.x - mean, d1 = x.y - mean, d2 = x.z - mean, d3 = x.w - mean;
    float sq = d0 * d0 + d1 * d1 + d2 * d2 + d3 * d3;
#pragma unroll
    for (int o = 16; o; o >>= 1) sq += __shfl_xor_sync(0xffffffffu, sq, o);
    const float istd = rsqrtf(sq * (1.0f / 128.0f) + 1e-5f);

    const float4 w = *reinterpret_cast<const float4*>(gn_w + h * HD + lane * 4);
    const float4 bb = *reinterpret_cast<const float4*>(gn_b + h * HD + lane * 4);
    float4 y;
    y.x = d0 * istd * w.x + bb.x;
    y.y = d1 * istd * w.y + bb.y;
    y.z = d2 * istd * w.z + bb.z;
    y.w = d3 * istd * w.w + bb.w;
    *reinterpret_cast<float4*>(out + off) = y;
}

// ---------------- launch ----------------
extern "C" void kernel_launch(void* const* d_in, const int* in_sizes, int n_in,
                              void* d_out, int out_size) {
    const float* q = (const float*)d_in[0];
    const float* k = (const float*)d_in[1];
    const float* v = (const float*)d_in[2];
    const float* Wi_w = (const float*)d_in[3];
    const float* Wi_b = (const float*)d_in[4];
    const float* Wf_w = (const float*)d_in[5];
    const float* Wf_b = (const float*)d_in[6];
    const float* gn_w = (const float*)d_in[7];
    const float* gn_b = (const float*)d_in[8];
    float* out = (float*)d_out;

    gates_kernel<<<SEQ, 256>>>(q, k, v, Wi_w, Wi_b, Wf_w, Wf_b);
    scan_kernel<<<NHEADS, 256>>>();

    cudaFuncSetAttribute(mlstm_mma, cudaFuncAttributeMaxDynamicSharedMemorySize, SMEM_TOTAL);
    dim3 grid(16, NHEADS);
    mlstm_mma<<<grid, 256, SMEM_TOTAL>>>();

    merge_gn<<<SEQ, 256>>>(out, gn_w, gn_b);
}

// round 17
// speedup vs baseline: 1.2249x; 1.0013x over previous
#include <cuda_runtime.h>
#include <cuda_fp16.h>
#include <cstdint>
#include <math.h>

#define SEQ 2048
#define DIM 1024
#define NHEADS 8
#define HD 128
#define LOG2E 1.4426950408889634f
#define INV_TAU 0.088388347648318447f

// ---------------- scratch (device globals; no allocation) ----------------
__device__ float g_itilde[NHEADS * SEQ];
__device__ float g_logsig[NHEADS * SEQ];
__device__ float g_a2[NHEADS * SEQ];      // a_j * log2(e)
__device__ float g_M2[NHEADS * SEQ];      // M_i * log2(e)
__device__ float g_nfloor[NHEADS * SEQ];  // exp(-(csum_i + M_i))
__device__ float g_tinfo[NHEADS][32][68]; // per (head, col-tile): ea[0..63], ref2, pad
__device__ __half g_o16[2][SEQ * DIM];    // fp16 partial O per column-parity
__device__ float g_bpart[2][NHEADS * SEQ];
__device__ __half g_q16[SEQ * DIM];       // fp16 copies (written by gates_kernel)
__device__ __half g_k16[SEQ * DIM];
__device__ __half g_v16[SEQ * DIM];

// ---------------- smem layout (bytes). Row pitch = 136 fp16 = 272 B ----------------
#define PITCH 272
#define OFF_Q 0            /* 128 x 272 = 34816 */
#define OFF_KV 34816       /* 3 buffers x (K 17408 + V 17408) */
#define KVB_STRIDE 34816
#define V_IN_BUF 17408
#define OFF_EA (OFF_KV + 3 * KVB_STRIDE)  /* 3 x 68 floats (tinfo per buffer) */
#define EAF (OFF_EA / 4)
#define SMEM_TOTAL (OFF_EA + 3 * 272)

// ---------------- helpers ----------------
__device__ __forceinline__ uint32_t smem_u32(const void* p) {
    uint32_t a;
    asm("{ .reg .u64 t; cvta.to.shared.u64 t, %1; cvt.u32.u64 %0, t; }" : "=r"(a) : "l"(p));
    return a;
}
__device__ __forceinline__ void cp16(uint32_t dst, const void* src) {
    asm volatile("cp.async.cg.shared.global [%0], [%1], 16;" :: "r"(dst), "l"(src));
}
#define CP_COMMIT() asm volatile("cp.async.commit_group;" ::: "memory")
#define CP_WAIT(n) asm volatile("cp.async.wait_group %0;" :: "n"(n) : "memory")
__device__ __forceinline__ void ldsm4(uint32_t* r, uint32_t addr) {
    asm volatile("ldmatrix.sync.aligned.m8n8.x4.shared.b16 {%0,%1,%2,%3}, [%4];"
                 : "=r"(r[0]), "=r"(r[1]), "=r"(r[2]), "=r"(r[3]) : "r"(addr));
}
__device__ __forceinline__ void ldsm4t(uint32_t* r, uint32_t addr) {
    asm volatile("ldmatrix.sync.aligned.m8n8.x4.trans.shared.b16 {%0,%1,%2,%3}, [%4];"
                 : "=r"(r[0]), "=r"(r[1]), "=r"(r[2]), "=r"(r[3]) : "r"(addr));
}
__device__ __forceinline__ void mma16816(float* d, const uint32_t* a, const uint32_t* b) {
    asm volatile(
        "mma.sync.aligned.m16n8k16.row.col.f32.f16.f16.f32 "
        "{%0,%1,%2,%3}, {%4,%5,%6,%7}, {%8,%9}, {%0,%1,%2,%3};"
        : "+f"(d[0]), "+f"(d[1]), "+f"(d[2]), "+f"(d[3])
        : "r"(a[0]), "r"(a[1]), "r"(a[2]), "r"(a[3]), "r"(b[0]), "r"(b[1]));
}
__device__ __forceinline__ uint32_t pack_hf2(float a, float b) {
    __half2 t = __floats2half2_rn(a, b);
    return *reinterpret_cast<uint32_t*>(&t);
}

// ---------------- kernel A: gate projections + fp16 conversion (1 token/block) ----------------
__global__ void gates_kernel(const float* __restrict__ q, const float* __restrict__ k,
                             const float* __restrict__ v,
                             const float* __restrict__ Wi_w, const float* __restrict__ Wi_b,
                             const float* __restrict__ Wf_w, const float* __restrict__ Wf_b) {
    const int s = blockIdx.x;
    const int h = threadIdx.x >> 5;
    const int lane = threadIdx.x & 31;
    const float* wi = Wi_w + h * 3 * DIM;
    const float* wf = Wf_w + h * 3 * DIM;
    const float* qr = q + (size_t)s * DIM;
    const float* kr = k + (size_t)s * DIM;
    const float* vr = v + (size_t)s * DIM;

    float si = 0.f, sf = 0.f;
#pragma unroll
    for (int m = 0; m < 8; m++) {
        const int d = m * 128 + lane * 4;
        const float4 xq = *reinterpret_cast<const float4*>(qr + d);
        const float4 xk = *reinterpret_cast<const float4*>(kr + d);
        const float4 xv = *reinterpret_cast<const float4*>(vr + d);

        if (h == 0) {
            *reinterpret_cast<uint2*>(g_q16 + (size_t)s * DIM + d) =
                make_uint2(pack_hf2(xq.x, xq.y), pack_hf2(xq.z, xq.w));
        } else if (h == 1) {
            *reinterpret_cast<uint2*>(g_k16 + (size_t)s * DIM + d) =
                make_uint2(pack_hf2(xk.x, xk.y), pack_hf2(xk.z, xk.w));
        } else if (h == 2) {
            *reinterpret_cast<uint2*>(g_v16 + (size_t)s * DIM + d) =
                make_uint2(pack_hf2(xv.x, xv.y), pack_hf2(xv.z, xv.w));
        }

        float4 w0 = *reinterpret_cast<const float4*>(wi + d);
        float4 w1 = *reinterpret_cast<const float4*>(wi + DIM + d);
        float4 w2 = *reinterpret_cast<const float4*>(wi + 2 * DIM + d);
        si += xq.x * w0.x + xq.y * w0.y + xq.z * w0.z + xq.w * w0.w;
        si += xk.x * w1.x + xk.y * w1.y + xk.z * w1.z + xk.w * w1.w;
        si += xv.x * w2.x + xv.y * w2.y + xv.z * w2.z + xv.w * w2.w;
        w0 = *reinterpret_cast<const float4*>(wf + d);
        w1 = *reinterpret_cast<const float4*>(wf + DIM + d);
        w2 = *reinterpret_cast<const float4*>(wf + 2 * DIM + d);
        sf += xq.x * w0.x + xq.y * w0.y + xq.z * w0.z + xq.w * w0.w;
        sf += xk.x * w1.x + xk.y * w1.y + xk.z * w1.z + xk.w * w1.w;
        sf += xv.x * w2.x + xv.y * w2.y + xv.z * w2.z + xv.w * w2.w;
    }
#pragma unroll
    for (int o = 16; o; o >>= 1) {
        si += __shfl_xor_sync(0xffffffffu, si, o);
        sf += __shfl_xor_sync(0xffffffffu, sf, o);
    }
    if (lane == 0) {
        g_itilde[h * SEQ + s] = si + Wi_b[h];
        const float ft = sf + Wf_b[h];
        g_logsig[h * SEQ + s] = fminf(ft, 0.f) - log1pf(__expf(-fabsf(ft)));
    }
}

// ---------------- kernel B: per-head scans + tile-info precompute (R15 verified) ----------------
__global__ void scan_kernel() {
    const int h = blockIdx.x;
    const int t = threadIdx.x;
    __shared__ float sc[256];

    float cs[8];
    float run = 0.f;
#pragma unroll
    for (int m = 0; m < 8; m++) {
        run += g_logsig[h * SEQ + t * 8 + m];
        cs[m] = run;
    }
    sc[t] = run;
    __syncthreads();
#pragma unroll
    for (int off = 1; off < 256; off <<= 1) {
        const float vv = sc[t];
        const float uu = (t >= off) ? sc[t - off] : 0.f;
        __syncthreads();
        sc[t] = vv + uu;
        __syncthreads();
    }
    const float base = (t == 0) ? 0.f : sc[t - 1];

    float a[8], amax[8], csum[8];
    float runm = -3.402823466e38f;
#pragma unroll
    for (int m = 0; m < 8; m++) {
        csum[m] = base + cs[m];
        a[m] = g_itilde[h * SEQ + t * 8 + m] - csum[m];
        runm = fmaxf(runm, a[m]);
        amax[m] = runm;
    }
    __syncthreads();
    sc[t] = runm;
    __syncthreads();
#pragma unroll
    for (int off = 1; off < 256; off <<= 1) {
        const float vv = sc[t];
        const float uu = (t >= off) ? sc[t - off] : -3.402823466e38f;
        __syncthreads();
        sc[t] = fmaxf(vv, uu);
        __syncthreads();
    }
    const float mbase = (t == 0) ? -3.402823466e38f : sc[t - 1];

    float a2v[8];
#pragma unroll
    for (int m = 0; m < 8; m++) {
        const int j = h * SEQ + t * 8 + m;
        const float Mv = fmaxf(mbase, amax[m]);
        a2v[m] = a[m] * LOG2E;
        g_a2[j] = a2v[m];
        g_M2[j] = Mv * LOG2E;
        g_nfloor[j] = exp2f(-(csum[m] + Mv) * LOG2E);
    }
    __syncthreads();  // g_M2 writes visible block-wide

    // tile info: thread t owns tokens t*8..t*8+7, all within tile (t>>3)
    {
        const int tile = t >> 3;
        const float ref2 = g_M2[h * SEQ + tile * 64 + 63];
#pragma unroll
        for (int m = 0; m < 8; m++)
            g_tinfo[h][tile][(t & 7) * 8 + m] = exp2f(a2v[m] - ref2);
        if ((t & 7) == 7) g_tinfo[h][tile][64] = ref2;
    }
}

// issue one K/V column tile (64 rows) + its tinfo into stage buffer via cp.async
__device__ __forceinline__ void issue_kv(uint32_t sb, int j0, int h, int hb,
                                         uint32_t kvb, uint32_t eaB, int tid) {
#pragma unroll
    for (int m = 0; m < 8; m++) {
        const int idx = tid + m * 256;          // 0..2047
        const int row = (idx >> 4) & 63;        // 64 rows per half
        const int chunk = idx & 15;             // 16 x 16B per row
        if (idx < 1024) {
            cp16(sb + kvb + row * PITCH + chunk * 16,
                 g_k16 + (size_t)(j0 + row) * DIM + h * HD + chunk * 8);
        } else {
            cp16(sb + kvb + V_IN_BUF + row * PITCH + chunk * 16,
                 g_v16 + (size_t)(j0 + row) * DIM + h * HD + chunk * 8);
        }
    }
    if (tid < 17)
        cp16(sb + eaB + tid * 16, &g_tinfo[h][j0 >> 6][tid * 4]);
}

// ---------------- main kernel: fp16 HMMA flash mLSTM, 3-stage pipeline ----------------
// grid (16, 8): blockIdx.x = pair p (>>1) + column parity (&1); blockIdx.y = head.
__global__ void __launch_bounds__(256, 1)
mlstm_mma() {
    extern __shared__ char smraw[];
    const uint32_t sb = smem_u32(smraw);
    float* smf = reinterpret_cast<float*>(smraw);

    const int tid = threadIdx.x;
    const int lane = tid & 31;
    const int warp = tid >> 5;
    const int qc = lane & 3;
    const int h = blockIdx.y, hb = h * SEQ;
    const int p = blockIdx.x >> 1, par = blockIdx.x & 1;
    const int m0 = warp * 16;

    const uint32_t offA = (uint32_t)(m0 + (lane & 15)) * PITCH + ((lane >> 4) * 8) * 2;
    const uint32_t offB = (uint32_t)(((lane >> 4) & 1) * 8 + (lane & 7)) * PITCH +
                          (((lane >> 3) & 1) * 8) * 2;
    const uint32_t offV = (uint32_t)(lane & 15) * PITCH + ((lane >> 4) * 8) * 2;

    for (int hs = 0; hs < 2; hs++) {
        const int rtc = hs ? (15 - p) : p;
        const int i0 = rtc * 128;
        const int n_ct = 2 * rtc + 2;

        if (hs) __syncthreads();  // protect Q/KV/ea buffers from previous half

        // --- prologue: group0 = Q + tile0, group1 = tile1 (possibly empty) ---
#pragma unroll
        for (int m = 0; m < 8; m++) {
            const int idx = tid + m * 256;      // 0..2047
            const int row = idx >> 4;           // 128 rows
            const int chunk = idx & 15;
            cp16(sb + OFF_Q + row * PITCH + chunk * 16,
                 g_q16 + (size_t)(i0 + row) * DIM + h * HD + chunk * 8);
        }
        issue_kv(sb, par * 64, h, hb, OFF_KV, OFF_EA, tid);
        CP_COMMIT();
        if (par + 2 < n_ct)
            issue_kv(sb, (par + 2) * 64, h, hb, OFF_KV + KVB_STRIDE, OFF_EA + 272, tid);
        CP_COMMIT();

        const int r_lo = i0 + m0 + (lane >> 2);
        const int r_hi = r_lo + 8;
        const float m2_lo = g_M2[hb + r_lo];
        const float m2_hi = g_M2[hb + r_hi];

        float accO[16][4];
#pragma unroll
        for (int a = 0; a < 16; a++)
#pragma unroll
            for (int b = 0; b < 4; b++) accO[a][b] = 0.f;
        float bsl = 0.f, bsh = 0.f;

        uint32_t qfrag[8][4];   // Q fragments, loaded once per half
        bool qloaded = false;

        for (int ct = par, it = 0; ct < n_ct; ct += 2, it++) {
            const int j0 = ct * 64;
            const int buf = it % 3;
            const uint32_t kvb = OFF_KV + (uint32_t)buf * KVB_STRIDE;
            const int eaF = EAF + buf * 68;

            CP_WAIT(1);        // tile it complete (1 newer group may stay pending)
            __syncthreads();   // publish tile it; all warps done with buffer (it+2)%3

            if (ct + 4 < n_ct) {
                const int nbuf = (it + 2) % 3;
                issue_kv(sb, (ct + 4) * 64, h, hb,
                         OFF_KV + (uint32_t)nbuf * KVB_STRIDE, OFF_EA + nbuf * 272, tid);
            }
            CP_COMMIT();       // always: uniform group accounting

            if (!qloaded) {
                qloaded = true;
#pragma unroll
                for (int kt = 0; kt < 8; kt++) ldsm4(qfrag[kt], sb + OFF_Q + offA + kt * 32);
            }

            const bool fskip = (ct == 2 * rtc + 1) && (warp < 4);
            if (!fskip) {
                // --- GEMM1: S = Q K^T (fp16, Q from registers) ---
                float accS[8][4];
#pragma unroll
                for (int a = 0; a < 8; a++)
#pragma unroll
                    for (int b = 0; b < 4; b++) accS[a][b] = 0.f;

#pragma unroll
                for (int kt = 0; kt < 8; kt++) {
#pragma unroll
                    for (int np2 = 0; np2 < 2; np2++) {
                        const uint32_t b0a = sb + kvb + offB + (2 * np2) * (16 * PITCH) + kt * 32;
                        const uint32_t b1a = b0a + 16 * PITCH;
                        uint32_t bh0[4], bh1[4];
                        ldsm4(bh0, b0a);
                        ldsm4(bh1, b1a);
                        float* a0 = accS[4 * np2];
                        float* a1 = accS[4 * np2 + 1];
                        float* a2 = accS[4 * np2 + 2];
                        float* a3 = accS[4 * np2 + 3];
                        mma16816(a0, qfrag[kt], bh0); mma16816(a2, qfrag[kt], bh1);
                        mma16816(a1, qfrag[kt], bh0 + 2); mma16816(a3, qfrag[kt], bh1 + 2);
                    }
                }

                // --- decay weights (incl. 1/tau) + causal mask + rowsum ---
                const float ref2 = smf[eaF + 64];
                const float em_lo = exp2f(ref2 - m2_lo) * INV_TAU;
                const float em_hi = exp2f(ref2 - m2_hi) * INV_TAU;
                const bool diag = (ct >= 2 * rtc);
#pragma unroll
                for (int nt = 0; nt < 8; nt++) {
                    const int col0 = nt * 8 + 2 * qc;
                    const float w0 = smf[eaF + col0], w1 = smf[eaF + col0 + 1];
                    float* c = accS[nt];
                    float p00 = c[0] * w0 * em_lo, p01 = c[1] * w1 * em_lo;
                    float p10 = c[2] * w0 * em_hi, p11 = c[3] * w1 * em_hi;
                    if (diag) {
                        const int jc = j0 + col0;
                        if (jc > r_lo) p00 = 0.f;
                        if (jc + 1 > r_lo) p01 = 0.f;
                        if (jc > r_hi) p10 = 0.f;
                        if (jc + 1 > r_hi) p11 = 0.f;
                    }
                    bsl += p00 + p01;
                    bsh += p10 + p11;
                    c[0] = p00; c[1] = p01; c[2] = p10; c[3] = p11;
                }

                // --- GEMM2: O += P V (fp16, interleaved accumulators) ---
#pragma unroll
                for (int kt2 = 0; kt2 < 4; kt2++) {
                    const float* s0 = accS[2 * kt2];
                    const float* s1 = accS[2 * kt2 + 1];
                    uint32_t ph[4];
                    ph[0] = pack_hf2(s0[0], s0[1]);
                    ph[1] = pack_hf2(s0[2], s0[3]);
                    ph[2] = pack_hf2(s1[0], s1[1]);
                    ph[3] = pack_hf2(s1[2], s1[3]);
#pragma unroll
                    for (int dpp = 0; dpp < 4; dpp++) {
                        const uint32_t v0a = sb + kvb + V_IN_BUF + offV + kt2 * (16 * PITCH) + (2 * dpp) * 32;
                        const uint32_t v1a = v0a + 32;
                        uint32_t vh0[4], vh1[4];
                        ldsm4t(vh0, v0a);
                        ldsm4t(vh1, v1a);
                        float* o0 = accO[4 * dpp];
                        float* o1 = accO[4 * dpp + 1];
                        float* o2 = accO[4 * dpp + 2];
                        float* o3 = accO[4 * dpp + 3];
                        mma16816(o0, ph, vh0); mma16816(o2, ph, vh1);
                        mma16816(o1, ph, vh0 + 2); mma16816(o3, ph, vh1 + 2);
                    }
                }
            }
        }

        // --- reduce rowsums across quad, store partials (fp16 O) ---
        bsl += __shfl_xor_sync(0xffffffffu, bsl, 1);
        bsl += __shfl_xor_sync(0xffffffffu, bsl, 2);
        bsh += __shfl_xor_sync(0xffffffffu, bsh, 1);
        bsh += __shfl_xor_sync(0xffffffffu, bsh, 2);
        if (qc == 0) {
            g_bpart[par][hb + r_lo] = bsl;
            g_bpart[par][hb + r_hi] = bsh;
        }
        __half* od = g_o16[par];
#pragma unroll
        for (int dt = 0; dt < 16; dt++) {
            const int col = h * HD + dt * 8 + 2 * qc;
            *reinterpret_cast<uint32_t*>(od + (size_t)r_lo * DIM + col) =
                pack_hf2(accO[dt][0], accO[dt][1]);
            *reinterpret_cast<uint32_t*>(od + (size_t)r_hi * DIM + col) =
                pack_hf2(accO[dt][2], accO[dt][3]);
        }
    }
}

// ---------------- merge + denominator + GroupNorm (2 tokens/block, interleaved) ----------------
__global__ void merge_gn(float* __restrict__ out, const float* __restrict__ gn_w,
                         const float* __restrict__ gn_b) {
    const int s0 = blockIdx.x * 2;
    const int h = threadIdx.x >> 5;
    const int lane = threadIdx.x & 31;
    const size_t off0 = (size_t)s0 * DIM + h * HD + lane * 4;
    const size_t off1 = off0 + DIM;

    // gather all loads first (max MLP)
    const uint2 ar0 = *reinterpret_cast<const uint2*>(g_o16[0] + off0);
    const uint2 br0 = *reinterpret_cast<const uint2*>(g_o16[1] + off0);
    const uint2 ar1 = *reinterpret_cast<const uint2*>(g_o16[0] + off1);
    const uint2 br1 = *reinterpret_cast<const uint2*>(g_o16[1] + off1);
    const float bs0 = g_bpart[0][h * SEQ + s0] + g_bpart[1][h * SEQ + s0];
    const float bs1 = g_bpart[0][h * SEQ + s0 + 1] + g_bpart[1][h * SEQ + s0 + 1];
    const float nf0 = g_nfloor[h * SEQ + s0];
    const float nf1 = g_nfloor[h * SEQ + s0 + 1];
    const float4 w = *reinterpret_cast<const float4*>(gn_w + h * HD + lane * 4);
    const float4 bb = *reinterpret_cast<const float4*>(gn_b + h * HD + lane * 4);

    const float inv0 = 1.0f / (fmaxf(fabsf(bs0), nf0) + 1e-6f);
    const float inv1 = 1.0f / (fmaxf(fabsf(bs1), nf1) + 1e-6f);

    const float2 a00 = __half22float2(*reinterpret_cast<const __half2*>(&ar0.x));
    const float2 a01 = __half22float2(*reinterpret_cast<const __half2*>(&ar0.y));
    const float2 b00 = __half22float2(*reinterpret_cast<const __half2*>(&br0.x));
    const float2 b01 = __half22float2(*reinterpret_cast<const __half2*>(&br0.y));
    const float2 a10 = __half22float2(*reinterpret_cast<const __half2*>(&ar1.x));
    const float2 a11 = __half22float2(*reinterpret_cast<const __half2*>(&ar1.y));
    const float2 b10 = __half22float2(*reinterpret_cast<const __half2*>(&br1.x));
    const float2 b11 = __half22float2(*reinterpret_cast<const __half2*>(&br1.y));

    float4 x0, x1;
    x0.x = (a00.x + b00.x) * inv0;
    x0.y = (a00.y + b00.y) * inv0;
    x0.z = (a01.x + b01.x) * inv0;
    x0.w = (a01.y + b01.y) * inv0;
    x1.x = (a10.x + b10.x) * inv1;
    x1.y = (a10.y + b10.y) * inv1;
    x1.z = (a11.x + b11.x) * inv1;
    x1.w = (a11.y + b11.y) * inv1;

    // interleaved shuffle reductions (two independent chains)
    float sum0 = x0.x + x0.y + x0.z + x0.w;
    float sum1 = x1.x + x1.y + x1.z + x1.w;
#pragma unroll
    for (int o = 16; o; o >>= 1) {
        sum0 += __shfl_xor_sync(0xffffffffu, sum0, o);
        sum1 += __shfl_xor_sync(0xffffffffu, sum1, o);
    }
    const float mean0 = sum0 * (1.0f / 128.0f);
    const float mean1 = sum1 * (1.0f / 128.0f);

    const float d00 = x0.x - mean0, d01 = x0.y - mean0, d02 = x0.z - mean0, d03 = x0.w - mean0;
    const float d10 = x1.x - mean1, d11 = x1.y - mean1, d12 = x1.z - mean1, d13 = x1.w - mean1;
    float sq0 = d00 * d00 + d01 * d01 + d02 * d02 + d03 * d03;
    float sq1 = d10 * d10 + d11 * d11 + d12 * d12 + d13 * d13;
#pragma unroll
    for (int o = 16; o; o >>= 1) {
        sq0 += __shfl_xor_sync(0xffffffffu, sq0, o);
        sq1 += __shfl_xor_sync(0xffffffffu, sq1, o);
    }
    const float istd0 = rsqrtf(sq0 * (1.0f / 128.0f) + 1e-5f);
    const float istd1 = rsqrtf(sq1 * (1.0f / 128.0f) + 1e-5f);

    float4 y0, y1;
    y0.x = d00 * istd0 * w.x + bb.x;
    y0.y = d01 * istd0 * w.y + bb.y;
    y0.z = d02 * istd0 * w.z + bb.z;
    y0.w = d03 * istd0 * w.w + bb.w;
    y1.x = d10 * istd1 * w.x + bb.x;
    y1.y = d11 * istd1 * w.y + bb.y;
    y1.z = d12 * istd1 * w.z + bb.z;
    y1.w = d13 * istd1 * w.w + bb.w;
    *reinterpret_cast<float4*>(out + off0) = y0;
    *reinterpret_cast<float4*>(out + off1) = y1;
}

// ---------------- launch ----------------
extern "C" void kernel_launch(void* const* d_in, const int* in_sizes, int n_in,
                              void* d_out, int out_size) {
    const float* q = (const float*)d_in[0];
    const float* k = (const float*)d_in[1];
    const float* v = (const float*)d_in[2];
    const float* Wi_w = (const float*)d_in[3];
    const float* Wi_b = (const float*)d_in[4];
    const float* Wf_w = (const float*)d_in[5];
    const float* Wf_b = (const float*)d_in[6];
    const float* gn_w = (const float*)d_in[7];
    const float* gn_b = (const float*)d_in[8];
    float* out = (float*)d_out;

    gates_kernel<<<SEQ, 256>>>(q, k, v, Wi_w, Wi_b, Wf_w, Wf_b);
    scan_kernel<<<NHEADS, 256>>>();

    cudaFuncSetAttribute(mlstm_mma, cudaFuncAttributeMaxDynamicSharedMemorySize, SMEM_TOTAL);
    dim3 grid(16, NHEADS);
    mlstm_mma<<<grid, 256, SMEM_TOTAL>>>();

    merge_gn<<<SEQ / 2, 256>>>(out, gn_w, gn_b);
}